// round 12
// baseline (speedup 1.0000x reference)
#include <cuda_runtime.h>
#include <cuda_bf16.h>
#include <cstddef>
#include <cstdint>

#define NB 8
#define NN 2048
#define NR 16384          // NB*NN rows
#define LRA 0.2f

typedef unsigned long long ull;

// ---------------- device scratch ----------------
__device__ float g_h[NR * 256];
__device__ __nv_bfloat16 g_Xhi[NR * 256];
__device__ __nv_bfloat16 g_Xlo[NR * 256];
__device__ __nv_bfloat16 g_Whi[2][256 * 256];
__device__ __nv_bfloat16 g_Wlo[2][256 * 256];
__device__ float g_bcat[2][256];
__device__ float g_aL[2][2][128];
__device__ float g_aR[2][2][128];
__device__ float g_hl[2 * NR];
__device__ float g_hr[2 * NR];
__device__ float g_rs[2 * NR];
__device__ int   g_sidx[2 * NR];
__device__ ull   g_kv[2 * NR];
__device__ float g_P1[2 * NR * 128];
__device__ float g_P2[2 * NR * 128];
__device__ float g_Z1[2 * NR];
__device__ float g_Z2[2 * NR];
__device__ float g_CS1[16][64][128];
__device__ float g_CS2[16][64][128];
__device__ float g_ZC1[16][64];
__device__ float g_ZC2[16][64];
__device__ unsigned g_barCnt = 0;
__device__ unsigned g_barGen = 0;

// ---------------- helpers ----------------
__device__ __forceinline__ uint32_t smem_u32(const void* p) {
    uint32_t a;
    asm("{ .reg .u64 tmp; cvta.to.shared.u64 tmp, %1; cvt.u32.u64 %0, tmp; }"
        : "=r"(a) : "l"(p));
    return a;
}
__device__ __forceinline__ void ldmx4(uint32_t* r, uint32_t addr) {
    asm volatile("ldmatrix.sync.aligned.m8n8.x4.shared.b16 {%0,%1,%2,%3}, [%4];"
        : "=r"(r[0]), "=r"(r[1]), "=r"(r[2]), "=r"(r[3]) : "r"(addr));
}
__device__ __forceinline__ void mma_bf16(float* c, const uint32_t* a, const uint32_t* b) {
    asm volatile("mma.sync.aligned.m16n8k16.row.col.f32.bf16.bf16.f32 "
        "{%0,%1,%2,%3}, {%4,%5,%6,%7}, {%8,%9}, {%0,%1,%2,%3};"
        : "+f"(c[0]), "+f"(c[1]), "+f"(c[2]), "+f"(c[3])
        : "r"(a[0]), "r"(a[1]), "r"(a[2]), "r"(a[3]), "r"(b[0]), "r"(b[1]));
}
__device__ __forceinline__ void cpa16(uint32_t dst, const void* src) {
    asm volatile("cp.async.cg.shared.global [%0], [%1], 16;" :: "r"(dst), "l"(src));
}
#define CP_COMMIT() asm volatile("cp.async.commit_group;" ::: "memory")
#define CP_WAIT1()  asm volatile("cp.async.wait_group 1;" ::: "memory")
#define CP_WAIT0()  asm volatile("cp.async.wait_group 0;" ::: "memory")

__device__ __forceinline__ void global_bar(unsigned nblk) {
    __syncthreads();
    if (threadIdx.x == 0) {
        unsigned gen = *(volatile unsigned*)&g_barGen;
        __threadfence();
        if (atomicAdd(&g_barCnt, 1u) == nblk - 1u) {
            g_barCnt = 0;
            __threadfence();
            atomicAdd(&g_barGen, 1u);
        } else {
            while (*(volatile unsigned*)&g_barGen == gen) __nanosleep(64);
        }
        __threadfence();
    }
    __syncthreads();
}

__device__ __forceinline__ void cvt_hilo(float4 v, uint2& hi, uint2& lo) {
    __nv_bfloat16 h0 = __float2bfloat16(v.x), h1 = __float2bfloat16(v.y);
    __nv_bfloat16 h2 = __float2bfloat16(v.z), h3 = __float2bfloat16(v.w);
    __nv_bfloat16 l0 = __float2bfloat16(v.x - __bfloat162float(h0));
    __nv_bfloat16 l1 = __float2bfloat16(v.y - __bfloat162float(h1));
    __nv_bfloat16 l2 = __float2bfloat16(v.z - __bfloat162float(h2));
    __nv_bfloat16 l3 = __float2bfloat16(v.w - __bfloat162float(h3));
    hi.x = ((uint32_t)__bfloat16_as_ushort(h1) << 16) | __bfloat16_as_ushort(h0);
    hi.y = ((uint32_t)__bfloat16_as_ushort(h3) << 16) | __bfloat16_as_ushort(h2);
    lo.x = ((uint32_t)__bfloat16_as_ushort(l1) << 16) | __bfloat16_as_ushort(l0);
    lo.y = ((uint32_t)__bfloat16_as_ushort(l3) << 16) | __bfloat16_as_ushort(l2);
}

// ---------------- pack + cvtX fused ----------------
__global__ __launch_bounds__(256) void pack_kernel(
    const float* x,
    const float* W00, const float* b00, const float* a00,
    const float* W01, const float* b01, const float* a01,
    const float* W10, const float* b10, const float* a10,
    const float* W11, const float* b11, const float* a11)
{
    const float* Ws[2][2] = {{W00, W01}, {W10, W11}};
    const float* bs[2][2] = {{b00, b01}, {b10, b11}};
    const float* as[2][2] = {{a00, a01}, {a10, a11}};
    int tid = blockIdx.x * blockDim.x + threadIdx.x;
    int nth = gridDim.x * blockDim.x;
    for (int idx = tid; idx < 2 * 256 * 256; idx += nth) {
        int layer = idx >> 16;
        int rem = idx & 0xFFFF;
        int n = rem >> 8, k = rem & 255;
        float w = Ws[layer][n >> 7][k * 128 + (n & 127)];
        __nv_bfloat16 h = __float2bfloat16(w);
        __nv_bfloat16 l = __float2bfloat16(w - __bfloat162float(h));
        g_Whi[layer][rem] = h;
        g_Wlo[layer][rem] = l;
    }
    for (int idx = tid; idx < 2 * 256; idx += nth) {
        int layer = idx >> 8, c = idx & 255;
        g_bcat[layer][c] = bs[layer][c >> 7][c & 127];
    }
    for (int idx = tid; idx < 2 * 2 * 128; idx += nth) {
        int layer = idx >> 8, head = (idx >> 7) & 1, d = idx & 127;
        g_aL[layer][head][d] = as[layer][head][d];
        g_aR[layer][head][d] = as[layer][head][128 + d];
    }
    int n4 = NR * 256 / 4;
    for (int i = tid; i < n4; i += nth) {
        float4 v = ((const float4*)x)[i];
        uint2 hi, lo;
        cvt_hilo(v, hi, lo);
        *(uint2*)&g_Xhi[i * 4] = hi;
        *(uint2*)&g_Xlo[i * 4] = lo;
    }
}

// ---------------- HMMA GEMM (3-pass bf16 split, cp.async double-buffer) -----
#define TILE_B 10240
__device__ __forceinline__ uint32_t tile_off(int b, int w) {
    return (uint32_t)((b * 4 + w) * TILE_B);
}
__device__ __forceinline__ void issue_tile(
    uint32_t sb, int bb, int m0, int n0, int k0, int t,
    const __nv_bfloat16* Whi, const __nv_bfloat16* Wlo)
{
#pragma unroll
    for (int q = 0; q < 2; q++) {
        int cid = t + q * 256;
        int row = cid >> 2, c8 = cid & 3;
        uint32_t soff = (uint32_t)(row * 80 + c8 * 16);
        size_t gx = (size_t)(m0 + row) * 256 + k0 + c8 * 8;
        size_t gw = (size_t)(n0 + row) * 256 + k0 + c8 * 8;
        cpa16(sb + tile_off(bb, 0) + soff, g_Xhi + gx);
        cpa16(sb + tile_off(bb, 1) + soff, g_Xlo + gx);
        cpa16(sb + tile_off(bb, 2) + soff, Whi + gw);
        cpa16(sb + tile_off(bb, 3) + soff, Wlo + gw);
    }
}

__global__ __launch_bounds__(256) void gemm_mma_kernel(int layer)
{
    extern __shared__ char smem[];
    __shared__ float sHL[128][2], sHR[128][2];
    uint32_t sb = smem_u32(smem);
    int t = threadIdx.x, lane = t & 31, wid = t >> 5;
    int wm = wid & 3, wn = wid >> 2;
    int m0 = blockIdx.y * 128, n0 = blockIdx.x * 128;
    int head = n0 >> 7;
    const __nv_bfloat16* Whi = g_Whi[layer];
    const __nv_bfloat16* Wlo = g_Wlo[layer];

    float acc[2][8][4];
#pragma unroll
    for (int mi = 0; mi < 2; mi++)
#pragma unroll
        for (int ni = 0; ni < 8; ni++)
#pragma unroll
            for (int q = 0; q < 4; q++) acc[mi][ni][q] = 0.f;

    int arow = wm * 32 + (lane & 7) + (lane & 8);
    int acolx = (lane & 16) >> 1;
    int brow4 = wn * 64 + (lane & 7) + ((lane & 16) >> 1);
    int bcol4 = (lane & 8);

    issue_tile(sb, 0, m0, n0, 0, t, Whi, Wlo);
    CP_COMMIT();

    for (int kt = 0; kt < 8; kt++) {
        int bb = kt & 1;
        if (kt < 7) {
            issue_tile(sb, bb ^ 1, m0, n0, (kt + 1) * 32, t, Whi, Wlo);
            CP_COMMIT();
            CP_WAIT1();
        } else {
            CP_WAIT0();
        }
        __syncthreads();
        uint32_t bA0 = sb + tile_off(bb, 0), bA1 = sb + tile_off(bb, 1);
        uint32_t bB0 = sb + tile_off(bb, 2), bB1 = sb + tile_off(bb, 3);
#pragma unroll
        for (int ks = 0; ks < 32; ks += 16) {
            uint32_t ah[2][4], al[2][4], bh[4][4], bl[4][4];
#pragma unroll
            for (int mi = 0; mi < 2; mi++) {
                uint32_t off = (uint32_t)((arow + mi * 16) * 40 + ks + acolx) * 2;
                ldmx4(ah[mi], bA0 + off);
                ldmx4(al[mi], bA1 + off);
            }
#pragma unroll
            for (int p = 0; p < 4; p++) {
                uint32_t off = (uint32_t)((brow4 + p * 16) * 40 + ks + bcol4) * 2;
                ldmx4(bh[p], bB0 + off);
                ldmx4(bl[p], bB1 + off);
            }
#pragma unroll
            for (int mi = 0; mi < 2; mi++)
#pragma unroll
                for (int ni = 0; ni < 8; ni++) {
                    const uint32_t* bph = &bh[ni >> 1][(ni & 1) * 2];
                    const uint32_t* bpl = &bl[ni >> 1][(ni & 1) * 2];
                    mma_bf16(acc[mi][ni], ah[mi], bph);
                    mma_bf16(acc[mi][ni], ah[mi], bpl);
                    mma_bf16(acc[mi][ni], al[mi], bph);
                }
        }
        __syncthreads();
    }

    int rbase = m0 + wm * 32 + (lane >> 2);
    int cloc = wn * 64 + (lane & 3) * 2;
    float pl[4] = {0.f, 0.f, 0.f, 0.f}, pr[4] = {0.f, 0.f, 0.f, 0.f};
#pragma unroll
    for (int mi = 0; mi < 2; mi++)
#pragma unroll
        for (int ni = 0; ni < 8; ni++) {
            int c0 = cloc + ni * 8;
            int gc = n0 + c0;
            float b0v = g_bcat[layer][gc], b1v = g_bcat[layer][gc + 1];
            float al0 = g_aL[layer][head][c0], al1 = g_aL[layer][head][c0 + 1];
            float ar0 = g_aR[layer][head][c0], ar1 = g_aR[layer][head][c0 + 1];
            int gr = rbase + mi * 16;
            float h00 = acc[mi][ni][0] + b0v, h01 = acc[mi][ni][1] + b1v;
            float h10 = acc[mi][ni][2] + b0v, h11 = acc[mi][ni][3] + b1v;
            float2 p0 = {h00, h01};
            float2 p1 = {h10, h11};
            *(float2*)&g_h[(size_t)gr * 256 + gc] = p0;
            *(float2*)&g_h[(size_t)(gr + 8) * 256 + gc] = p1;
            pl[mi * 2 + 0] += h00 * al0 + h01 * al1;
            pl[mi * 2 + 1] += h10 * al0 + h11 * al1;
            pr[mi * 2 + 0] += h00 * ar0 + h01 * ar1;
            pr[mi * 2 + 1] += h10 * ar0 + h11 * ar1;
        }
#pragma unroll
    for (int off = 1; off < 4; off <<= 1)
#pragma unroll
        for (int r = 0; r < 4; r++) {
            pl[r] += __shfl_xor_sync(0xFFFFFFFFu, pl[r], off);
            pr[r] += __shfl_xor_sync(0xFFFFFFFFu, pr[r], off);
        }
    if ((lane & 3) == 0) {
        int rloc = wm * 32 + (lane >> 2);
#pragma unroll
        for (int r = 0; r < 4; r++) {
            sHL[rloc + r * 8][wn] = pl[r];
            sHR[rloc + r * 8][wn] = pr[r];
        }
    }
    __syncthreads();
    if (t < 128) {
        g_hl[head * NR + m0 + t] = sHL[t][0] + sHL[t][1];
        g_hr[head * NR + m0 + t] = sHR[t][0] + sHR[t][1];
    }
}

// ---------------- sort stage 1 ----------------
__device__ __forceinline__ ull bswap_reg(ull v, int j, bool up, int i) {
    ull pv = __shfl_xor_sync(0xFFFFFFFFu, v, j);
    bool lower = ((i & j) == 0);
    return (lower == up) ? (v < pv ? v : pv) : (v > pv ? v : pv);
}

__global__ __launch_bounds__(512) void sortA_kernel()
{
    __shared__ ull kv[512];
    int bid = blockIdx.x;
    int sg = bid >> 2, r = bid & 3;
    int base = (sg >> 3) * NR + (sg & 7) * 2048;
    int i = threadIdx.x;
    int gi = r * 512 + i;

    unsigned u = __float_as_uint(g_hr[base + gi]);
    u ^= (u >> 31) ? 0xFFFFFFFFu : 0x80000000u;
    ull v = ((ull)u << 32) | (unsigned)gi;

#pragma unroll
    for (int k = 2; k <= 32; k <<= 1) {
        bool up = ((i & k) == 0);
        for (int j = k >> 1; j >= 1; j >>= 1)
            v = bswap_reg(v, j, up, i);
    }
    kv[i] = v;
    __syncthreads();

    for (int k = 64; k <= 512; k <<= 1) {
        for (int j = k >> 1; j >= 32; j >>= 1) {
            int ixj = i ^ j;
            if (ixj > i) {
                bool up = ((i & k) == 0);
                ull a = kv[i], b = kv[ixj];
                if ((a > b) == up) { kv[i] = b; kv[ixj] = a; }
            }
            __syncthreads();
        }
        v = kv[i];
        bool up = ((i & k) == 0);
        for (int j = 16; j >= 1; j >>= 1)
            v = bswap_reg(v, j, up, i);
        if (k < 512) { kv[i] = v; __syncthreads(); }
    }
    g_kv[base + gi] = v;
}

// ---------------- sort stage 2: rank merge (smem-staged) ----------------
__global__ __launch_bounds__(512) void sortB_kernel()
{
    __shared__ ull runs[2048];
    int bid = blockIdx.x;
    int sg = bid >> 2, r = bid & 3;
    int base = (sg >> 3) * NR + (sg & 7) * 2048;
    int i = threadIdx.x;
#pragma unroll
    for (int q = 0; q < 4; q++)
        runs[i + q * 512] = g_kv[base + i + q * 512];
    __syncthreads();

    ull v = runs[r * 512 + i];
    int rank = i;
#pragma unroll
    for (int rr = 0; rr < 4; rr++) {
        if (rr == r) continue;
        const ull* run = &runs[rr * 512];
        int lo = 0, hi = 512;
#pragma unroll
        for (int s = 0; s < 10; s++) {
            if (lo < hi) {
                int mid = (lo + hi) >> 1;
                if (run[mid] < v) lo = mid + 1; else hi = mid;
            }
        }
        rank += lo;
    }
    unsigned u = (unsigned)(v >> 32);
    u ^= (u >> 31) ? 0x80000000u : 0xFFFFFFFFu;
    g_rs[base + rank] = __uint_as_float(u);
    g_sidx[base + rank] = (int)(v & 0xFFFFFFFFu);
}

// ---------------- fused prefix + lookup (grid 256 x 256, all resident) -----
#define ATTN_BLOCKS 256
__global__ __launch_bounds__(256, 2) void attn_kernel(float* xout)
{
    __shared__ float s_ew1[2][2][32], s_ew2[2][2][32];
    __shared__ int   s_sid[2][2][32];
    __shared__ float s_ec[2][16], s_eac[2][16], s_wii[2][16], s_idn[2][16];
    __shared__ int   s_m[2][16];
    int t = threadIdx.x;
    int half = t >> 7, d = t & 127;
    float v[2][32];

    // ---- phase 1: gather + chunk sums (2 tasks per block) ----
#pragma unroll
    for (int slot = 0; slot < 2; slot++) {
        int task = blockIdx.x + slot * ATTN_BLOCKS;  // 0..511
        int hb = task >> 5, pair = task & 31;
        int head = hb >> 3, b = hb & 7;
        int base = head * NR + b * 2048;
        if (t < 64) {
            int ch = t >> 5, jj = t & 31;
            float r = g_rs[base + (2 * pair + ch) * 32 + jj];
            s_ew1[slot][ch][jj] = expf(r);
            s_ew2[slot][ch][jj] = expf(LRA * r);
            s_sid[slot][ch][jj] = g_sidx[base + (2 * pair + ch) * 32 + jj];
        }
        __syncthreads();
        int chunk = 2 * pair + half;
        const float* hp = g_h + (size_t)(b * 2048) * 256 + head * 128 + d;
        float a1 = 0.f, a2 = 0.f, z1 = 0.f, z2 = 0.f;
#pragma unroll
        for (int j = 0; j < 32; j++) {
            float x = __ldg(hp + (size_t)s_sid[slot][half][j] * 256);
            v[slot][j] = x;
            float w1 = s_ew1[slot][half][j], w2 = s_ew2[slot][half][j];
            a1 = fmaf(w1, x, a1);
            a2 = fmaf(w2, x, a2);
            if (d == 0) { z1 += w1; z2 += w2; }
        }
        g_CS1[hb][chunk][d] = a1;
        g_CS2[hb][chunk][d] = a2;
        if (d == 0) { g_ZC1[hb][chunk] = z1; g_ZC2[hb][chunk] = z2; }
        __syncthreads();
    }

    global_bar(ATTN_BLOCKS);

    // ---- phase 2: carries + write full prefixes from registers ----
#pragma unroll
    for (int slot = 0; slot < 2; slot++) {
        int task = blockIdx.x + slot * ATTN_BLOCKS;
        int hb = task >> 5, pair = task & 31;
        int head = hb >> 3, b = hb & 7;
        int base = head * NR + b * 2048;
        int chunk = 2 * pair + half;
        int j0 = chunk * 32;
        float a1 = 0.f, a2 = 0.f, z1 = 0.f, z2 = 0.f;
#pragma unroll 8
        for (int c = 0; c < chunk; c++) {
            a1 += g_CS1[hb][c][d];
            a2 += g_CS2[hb][c][d];
            if (d == 0) { z1 += g_ZC1[hb][c]; z2 += g_ZC2[hb][c]; }
        }
        float* P1 = g_P1 + (size_t)base * 128 + d;
        float* P2 = g_P2 + (size_t)base * 128 + d;
#pragma unroll
        for (int j = 0; j < 32; j++) {
            float x = v[slot][j];
            float w1 = s_ew1[slot][half][j], w2 = s_ew2[slot][half][j];
            a1 = fmaf(w1, x, a1);
            a2 = fmaf(w2, x, a2);
            P1[(size_t)(j0 + j) * 128] = a1;
            P2[(size_t)(j0 + j) * 128] = a2;
            if (d == 0) {
                z1 += w1; z2 += w2;
                g_Z1[base + j0 + j] = z1;
                g_Z2[base + j0 + j] = z2;
            }
        }
    }

    global_bar(ATTN_BLOCKS);

    // ---- phase 3: lookup (4 tasks per block) ----
    for (int q = 0; q < 4; q++) {
        int task = blockIdx.x + q * ATTN_BLOCKS;   // 0..1023
        int b = task & 7;
        int n0 = (task >> 3) * 16;
        if (t < 32) {
            int hh = t >> 4, nn = t & 15;
            int bb = hh * NR + b * 2048;
            int row = b * 2048 + n0 + nn;
            float c = g_hl[hh * NR + row];
            float ri = g_hr[hh * NR + row];
            float thr = -c;
            const float* rs = &g_rs[bb];
            int lo = 0, hi = 2048;
            while (lo < hi) {
                int mid = (lo + hi) >> 1;
                if (rs[mid] < thr) lo = mid + 1; else hi = mid;
            }
            int m = lo;
            float ec = expf(c), eac = expf(LRA * c);
            float wii = (ri < thr) ? eac * expf(LRA * ri) : ec * expf(ri);
            float z1tot = g_Z1[bb + 2047];
            float Z1m = (m > 0) ? g_Z1[bb + m - 1] : 0.f;
            float Z2m = (m > 0) ? g_Z2[bb + m - 1] : 0.f;
            float denom = ec * (z1tot - Z1m) + eac * Z2m - wii;
            s_m[hh][nn] = m;
            s_ec[hh][nn] = ec;
            s_eac[hh][nn] = eac;
            s_wii[hh][nn] = wii;
            s_idn[hh][nn] = 1.f / denom;
        }
        __syncthreads();
        int head = half;
        int base = head * NR + b * 2048;
        float p1tot = g_P1[((size_t)base + 2047) * 128 + d];
#pragma unroll 2
        for (int nn = 0; nn < 16; nn++) {
            int row = b * 2048 + n0 + nn;
            int m = s_m[head][nn];
            float ec = s_ec[head][nn], eac = s_eac[head][nn];
            float wii = s_wii[head][nn], idn = s_idn[head][nn];
            size_t idx = (size_t)row * 256 + head * 128 + d;
            float hid = g_h[idx];
            float P1m = 0.f, P2m = 0.f;
            if (m > 0) {
                size_t off = ((size_t)base + m - 1) * 128 + d;
                P1m = g_P1[off];
                P2m = g_P2[off];
            }
            float numer = ec * (p1tot - P1m) + eac * P2m - wii * hid;
            float o = numer * idn + hid;
            float res = (o > 0.f) ? o : expm1f(o);
            if (xout) {
                xout[idx] = res;
            } else {
                __nv_bfloat16 h = __float2bfloat16(res);
                __nv_bfloat16 l = __float2bfloat16(res - __bfloat162float(h));
                g_Xhi[idx] = h;
                g_Xlo[idx] = l;
            }
        }
        __syncthreads();
    }
}

// ---------------- launch ----------------
extern "C" void kernel_launch(void* const* d_in, const int* in_sizes, int n_in,
                              void* d_out, int out_size)
{
    const float* x   = (const float*)d_in[0];
    const float* W00 = (const float*)d_in[2];
    const float* b00 = (const float*)d_in[3];
    const float* a00 = (const float*)d_in[4];
    const float* W01 = (const float*)d_in[5];
    const float* b01 = (const float*)d_in[6];
    const float* a01 = (const float*)d_in[7];
    const float* W10 = (const float*)d_in[8];
    const float* b10 = (const float*)d_in[9];
    const float* a10 = (const float*)d_in[10];
    const float* W11 = (const float*)d_in[11];
    const float* b11 = (const float*)d_in[12];
    const float* a11 = (const float*)d_in[13];
    float* out = (float*)d_out;

    const int GEMM_SMEM = 8 * TILE_B;
    cudaFuncSetAttribute(gemm_mma_kernel,
                         cudaFuncAttributeMaxDynamicSharedMemorySize, GEMM_SMEM);

    pack_kernel<<<512, 256>>>(x, W00, b00, a00, W01, b01, a01,
                              W10, b10, a10, W11, b11, a11);

    // layer 0
    gemm_mma_kernel<<<dim3(2, 128), 256, GEMM_SMEM>>>(0);
    sortA_kernel<<<64, 512>>>();
    sortB_kernel<<<64, 512>>>();
    attn_kernel<<<ATTN_BLOCKS, 256>>>(nullptr);

    // layer 1
    gemm_mma_kernel<<<dim3(2, 128), 256, GEMM_SMEM>>>(1);
    sortA_kernel<<<64, 512>>>();
    sortB_kernel<<<64, 512>>>();
    attn_kernel<<<ATTN_BLOCKS, 256>>>(out);
}

// round 13
// speedup vs baseline: 1.8609x; 1.8609x over previous
#include <cuda_runtime.h>
#include <cuda_bf16.h>
#include <cstddef>
#include <cstdint>

#define NB 8
#define NN 2048
#define NR 16384          // NB*NN rows
#define LRA 0.2f

typedef unsigned long long ull;

// ---------------- device scratch ----------------
__device__ float g_h[NR * 256];
__device__ __nv_bfloat16 g_Xhi[NR * 256];
__device__ __nv_bfloat16 g_Xlo[NR * 256];
__device__ __nv_bfloat16 g_Whi[2][256 * 256];
__device__ __nv_bfloat16 g_Wlo[2][256 * 256];
__device__ float g_bcat[2][256];
__device__ float g_aL[2][2][128];
__device__ float g_aR[2][2][128];
__device__ float g_hl[2 * NR];
__device__ float g_hr[2 * NR];
__device__ float g_rs[2 * NR];
__device__ int   g_sidx[2 * NR];
__device__ ull   g_kv[2 * NR];
__device__ float2 g_P12[2 * NR * 128];  // interleaved {P1,P2}
__device__ float2 g_Z12[2 * NR];        // interleaved {Z1,Z2}
__device__ float g_CS1[16][64][128];
__device__ float g_CS2[16][64][128];
__device__ float g_ZC1[16][64];
__device__ float g_ZC2[16][64];

// ---------------- helpers ----------------
__device__ __forceinline__ uint32_t smem_u32(const void* p) {
    uint32_t a;
    asm("{ .reg .u64 tmp; cvta.to.shared.u64 tmp, %1; cvt.u32.u64 %0, tmp; }"
        : "=r"(a) : "l"(p));
    return a;
}
__device__ __forceinline__ void ldmx4(uint32_t* r, uint32_t addr) {
    asm volatile("ldmatrix.sync.aligned.m8n8.x4.shared.b16 {%0,%1,%2,%3}, [%4];"
        : "=r"(r[0]), "=r"(r[1]), "=r"(r[2]), "=r"(r[3]) : "r"(addr));
}
__device__ __forceinline__ void mma_bf16(float* c, const uint32_t* a, const uint32_t* b) {
    asm volatile("mma.sync.aligned.m16n8k16.row.col.f32.bf16.bf16.f32 "
        "{%0,%1,%2,%3}, {%4,%5,%6,%7}, {%8,%9}, {%0,%1,%2,%3};"
        : "+f"(c[0]), "+f"(c[1]), "+f"(c[2]), "+f"(c[3])
        : "r"(a[0]), "r"(a[1]), "r"(a[2]), "r"(a[3]), "r"(b[0]), "r"(b[1]));
}
__device__ __forceinline__ void cpa16(uint32_t dst, const void* src) {
    asm volatile("cp.async.cg.shared.global [%0], [%1], 16;" :: "r"(dst), "l"(src));
}
#define CP_COMMIT() asm volatile("cp.async.commit_group;" ::: "memory")
#define CP_WAIT1()  asm volatile("cp.async.wait_group 1;" ::: "memory")
#define CP_WAIT0()  asm volatile("cp.async.wait_group 0;" ::: "memory")

__device__ __forceinline__ void cvt_hilo(float4 v, uint2& hi, uint2& lo) {
    __nv_bfloat16 h0 = __float2bfloat16(v.x), h1 = __float2bfloat16(v.y);
    __nv_bfloat16 h2 = __float2bfloat16(v.z), h3 = __float2bfloat16(v.w);
    __nv_bfloat16 l0 = __float2bfloat16(v.x - __bfloat162float(h0));
    __nv_bfloat16 l1 = __float2bfloat16(v.y - __bfloat162float(h1));
    __nv_bfloat16 l2 = __float2bfloat16(v.z - __bfloat162float(h2));
    __nv_bfloat16 l3 = __float2bfloat16(v.w - __bfloat162float(h3));
    hi.x = ((uint32_t)__bfloat16_as_ushort(h1) << 16) | __bfloat16_as_ushort(h0);
    hi.y = ((uint32_t)__bfloat16_as_ushort(h3) << 16) | __bfloat16_as_ushort(h2);
    lo.x = ((uint32_t)__bfloat16_as_ushort(l1) << 16) | __bfloat16_as_ushort(l0);
    lo.y = ((uint32_t)__bfloat16_as_ushort(l3) << 16) | __bfloat16_as_ushort(l2);
}

// ---------------- pack + cvtX fused ----------------
__global__ __launch_bounds__(256) void pack_kernel(
    const float* x,
    const float* W00, const float* b00, const float* a00,
    const float* W01, const float* b01, const float* a01,
    const float* W10, const float* b10, const float* a10,
    const float* W11, const float* b11, const float* a11)
{
    const float* Ws[2][2] = {{W00, W01}, {W10, W11}};
    const float* bs[2][2] = {{b00, b01}, {b10, b11}};
    const float* as[2][2] = {{a00, a01}, {a10, a11}};
    int tid = blockIdx.x * blockDim.x + threadIdx.x;
    int nth = gridDim.x * blockDim.x;
    for (int idx = tid; idx < 2 * 256 * 256; idx += nth) {
        int layer = idx >> 16;
        int rem = idx & 0xFFFF;
        int n = rem >> 8, k = rem & 255;
        float w = Ws[layer][n >> 7][k * 128 + (n & 127)];
        __nv_bfloat16 h = __float2bfloat16(w);
        __nv_bfloat16 l = __float2bfloat16(w - __bfloat162float(h));
        g_Whi[layer][rem] = h;
        g_Wlo[layer][rem] = l;
    }
    for (int idx = tid; idx < 2 * 256; idx += nth) {
        int layer = idx >> 8, c = idx & 255;
        g_bcat[layer][c] = bs[layer][c >> 7][c & 127];
    }
    for (int idx = tid; idx < 2 * 2 * 128; idx += nth) {
        int layer = idx >> 8, head = (idx >> 7) & 1, d = idx & 127;
        g_aL[layer][head][d] = as[layer][head][d];
        g_aR[layer][head][d] = as[layer][head][128 + d];
    }
    int n4 = NR * 256 / 4;
    for (int i = tid; i < n4; i += nth) {
        float4 v = ((const float4*)x)[i];
        uint2 hi, lo;
        cvt_hilo(v, hi, lo);
        *(uint2*)&g_Xhi[i * 4] = hi;
        *(uint2*)&g_Xlo[i * 4] = lo;
    }
}

// ---------------- HMMA GEMM (3-pass bf16 split, cp.async double-buffer) -----
#define TILE_B 10240
__device__ __forceinline__ uint32_t tile_off(int b, int w) {
    return (uint32_t)((b * 4 + w) * TILE_B);
}
__device__ __forceinline__ void issue_tile(
    uint32_t sb, int bb, int m0, int n0, int k0, int t,
    const __nv_bfloat16* Whi, const __nv_bfloat16* Wlo)
{
#pragma unroll
    for (int q = 0; q < 2; q++) {
        int cid = t + q * 256;
        int row = cid >> 2, c8 = cid & 3;
        uint32_t soff = (uint32_t)(row * 80 + c8 * 16);
        size_t gx = (size_t)(m0 + row) * 256 + k0 + c8 * 8;
        size_t gw = (size_t)(n0 + row) * 256 + k0 + c8 * 8;
        cpa16(sb + tile_off(bb, 0) + soff, g_Xhi + gx);
        cpa16(sb + tile_off(bb, 1) + soff, g_Xlo + gx);
        cpa16(sb + tile_off(bb, 2) + soff, Whi + gw);
        cpa16(sb + tile_off(bb, 3) + soff, Wlo + gw);
    }
}

__global__ __launch_bounds__(256) void gemm_mma_kernel(int layer)
{
    extern __shared__ char smem[];
    __shared__ float sHL[128][2], sHR[128][2];
    uint32_t sb = smem_u32(smem);
    int t = threadIdx.x, lane = t & 31, wid = t >> 5;
    int wm = wid & 3, wn = wid >> 2;
    int m0 = blockIdx.y * 128, n0 = blockIdx.x * 128;
    int head = n0 >> 7;
    const __nv_bfloat16* Whi = g_Whi[layer];
    const __nv_bfloat16* Wlo = g_Wlo[layer];

    float acc[2][8][4];
#pragma unroll
    for (int mi = 0; mi < 2; mi++)
#pragma unroll
        for (int ni = 0; ni < 8; ni++)
#pragma unroll
            for (int q = 0; q < 4; q++) acc[mi][ni][q] = 0.f;

    int arow = wm * 32 + (lane & 7) + (lane & 8);
    int acolx = (lane & 16) >> 1;
    int brow4 = wn * 64 + (lane & 7) + ((lane & 16) >> 1);
    int bcol4 = (lane & 8);

    issue_tile(sb, 0, m0, n0, 0, t, Whi, Wlo);
    CP_COMMIT();

    for (int kt = 0; kt < 8; kt++) {
        int bb = kt & 1;
        if (kt < 7) {
            issue_tile(sb, bb ^ 1, m0, n0, (kt + 1) * 32, t, Whi, Wlo);
            CP_COMMIT();
            CP_WAIT1();
        } else {
            CP_WAIT0();
        }
        __syncthreads();
        uint32_t bA0 = sb + tile_off(bb, 0), bA1 = sb + tile_off(bb, 1);
        uint32_t bB0 = sb + tile_off(bb, 2), bB1 = sb + tile_off(bb, 3);
#pragma unroll
        for (int ks = 0; ks < 32; ks += 16) {
            uint32_t ah[2][4], al[2][4], bh[4][4], bl[4][4];
#pragma unroll
            for (int mi = 0; mi < 2; mi++) {
                uint32_t off = (uint32_t)((arow + mi * 16) * 40 + ks + acolx) * 2;
                ldmx4(ah[mi], bA0 + off);
                ldmx4(al[mi], bA1 + off);
            }
#pragma unroll
            for (int p = 0; p < 4; p++) {
                uint32_t off = (uint32_t)((brow4 + p * 16) * 40 + ks + bcol4) * 2;
                ldmx4(bh[p], bB0 + off);
                ldmx4(bl[p], bB1 + off);
            }
#pragma unroll
            for (int mi = 0; mi < 2; mi++)
#pragma unroll
                for (int ni = 0; ni < 8; ni++) {
                    const uint32_t* bph = &bh[ni >> 1][(ni & 1) * 2];
                    const uint32_t* bpl = &bl[ni >> 1][(ni & 1) * 2];
                    mma_bf16(acc[mi][ni], ah[mi], bph);
                    mma_bf16(acc[mi][ni], ah[mi], bpl);
                    mma_bf16(acc[mi][ni], al[mi], bph);
                }
        }
        __syncthreads();
    }

    int rbase = m0 + wm * 32 + (lane >> 2);
    int cloc = wn * 64 + (lane & 3) * 2;
    float pl[4] = {0.f, 0.f, 0.f, 0.f}, pr[4] = {0.f, 0.f, 0.f, 0.f};
#pragma unroll
    for (int mi = 0; mi < 2; mi++)
#pragma unroll
        for (int ni = 0; ni < 8; ni++) {
            int c0 = cloc + ni * 8;
            int gc = n0 + c0;
            float b0v = g_bcat[layer][gc], b1v = g_bcat[layer][gc + 1];
            float al0 = g_aL[layer][head][c0], al1 = g_aL[layer][head][c0 + 1];
            float ar0 = g_aR[layer][head][c0], ar1 = g_aR[layer][head][c0 + 1];
            int gr = rbase + mi * 16;
            float h00 = acc[mi][ni][0] + b0v, h01 = acc[mi][ni][1] + b1v;
            float h10 = acc[mi][ni][2] + b0v, h11 = acc[mi][ni][3] + b1v;
            float2 p0 = {h00, h01};
            float2 p1 = {h10, h11};
            *(float2*)&g_h[(size_t)gr * 256 + gc] = p0;
            *(float2*)&g_h[(size_t)(gr + 8) * 256 + gc] = p1;
            pl[mi * 2 + 0] += h00 * al0 + h01 * al1;
            pl[mi * 2 + 1] += h10 * al0 + h11 * al1;
            pr[mi * 2 + 0] += h00 * ar0 + h01 * ar1;
            pr[mi * 2 + 1] += h10 * ar0 + h11 * ar1;
        }
#pragma unroll
    for (int off = 1; off < 4; off <<= 1)
#pragma unroll
        for (int r = 0; r < 4; r++) {
            pl[r] += __shfl_xor_sync(0xFFFFFFFFu, pl[r], off);
            pr[r] += __shfl_xor_sync(0xFFFFFFFFu, pr[r], off);
        }
    if ((lane & 3) == 0) {
        int rloc = wm * 32 + (lane >> 2);
#pragma unroll
        for (int r = 0; r < 4; r++) {
            sHL[rloc + r * 8][wn] = pl[r];
            sHR[rloc + r * 8][wn] = pr[r];
        }
    }
    __syncthreads();
    if (t < 128) {
        g_hl[head * NR + m0 + t] = sHL[t][0] + sHL[t][1];
        g_hr[head * NR + m0 + t] = sHR[t][0] + sHR[t][1];
    }
}

// ---------------- sort stage 1 ----------------
__device__ __forceinline__ ull bswap_reg(ull v, int j, bool up, int i) {
    ull pv = __shfl_xor_sync(0xFFFFFFFFu, v, j);
    bool lower = ((i & j) == 0);
    return (lower == up) ? (v < pv ? v : pv) : (v > pv ? v : pv);
}

__global__ __launch_bounds__(512) void sortA_kernel()
{
    __shared__ ull kv[512];
    int bid = blockIdx.x;
    int sg = bid >> 2, r = bid & 3;
    int base = (sg >> 3) * NR + (sg & 7) * 2048;
    int i = threadIdx.x;
    int gi = r * 512 + i;

    unsigned u = __float_as_uint(g_hr[base + gi]);
    u ^= (u >> 31) ? 0xFFFFFFFFu : 0x80000000u;
    ull v = ((ull)u << 32) | (unsigned)gi;

#pragma unroll
    for (int k = 2; k <= 32; k <<= 1) {
        bool up = ((i & k) == 0);
        for (int j = k >> 1; j >= 1; j >>= 1)
            v = bswap_reg(v, j, up, i);
    }
    kv[i] = v;
    __syncthreads();

    for (int k = 64; k <= 512; k <<= 1) {
        for (int j = k >> 1; j >= 32; j >>= 1) {
            int ixj = i ^ j;
            if (ixj > i) {
                bool up = ((i & k) == 0);
                ull a = kv[i], b = kv[ixj];
                if ((a > b) == up) { kv[i] = b; kv[ixj] = a; }
            }
            __syncthreads();
        }
        v = kv[i];
        bool up = ((i & k) == 0);
        for (int j = 16; j >= 1; j >>= 1)
            v = bswap_reg(v, j, up, i);
        if (k < 512) { kv[i] = v; __syncthreads(); }
    }
    g_kv[base + gi] = v;
}

// ---------------- sort stage 2: rank merge (smem-staged) ----------------
__global__ __launch_bounds__(512) void sortB_kernel()
{
    __shared__ ull runs[2048];
    int bid = blockIdx.x;
    int sg = bid >> 2, r = bid & 3;
    int base = (sg >> 3) * NR + (sg & 7) * 2048;
    int i = threadIdx.x;
#pragma unroll
    for (int q = 0; q < 4; q++)
        runs[i + q * 512] = g_kv[base + i + q * 512];
    __syncthreads();

    ull v = runs[r * 512 + i];
    int rank = i;
#pragma unroll
    for (int rr = 0; rr < 4; rr++) {
        if (rr == r) continue;
        const ull* run = &runs[rr * 512];
        int lo = 0, hi = 512;
#pragma unroll
        for (int s = 0; s < 10; s++) {
            if (lo < hi) {
                int mid = (lo + hi) >> 1;
                if (run[mid] < v) lo = mid + 1; else hi = mid;
            }
        }
        rank += lo;
    }
    unsigned u = (unsigned)(v >> 32);
    u ^= (u >> 31) ? 0x80000000u : 0xFFFFFFFFu;
    g_rs[base + rank] = __uint_as_float(u);
    g_sidx[base + rank] = (int)(v & 0xFFFFFFFFu);
}

// ---------------- chunked prefix pass A: per-chunk (32) sums, grid 512 -------
__global__ __launch_bounds__(256) void prefixA_kernel()
{
    __shared__ float ew1[2][32], ew2[2][32];
    __shared__ int   sid[2][32];
    int blk = blockIdx.x;
    int hb = blk >> 5, pair = blk & 31;
    int head = hb >> 3, b = hb & 7;
    int base = head * NR + b * 2048;
    int t = threadIdx.x;
    if (t < 64) {
        int ch = t >> 5, jj = t & 31;
        float r = g_rs[base + (2 * pair + ch) * 32 + jj];
        ew1[ch][jj] = expf(r);
        ew2[ch][jj] = expf(LRA * r);
        sid[ch][jj] = g_sidx[base + (2 * pair + ch) * 32 + jj];
    }
    __syncthreads();
    int half = t >> 7, d = t & 127;
    int chunk = 2 * pair + half;
    const float* hp = g_h + (size_t)(b * 2048) * 256 + head * 128 + d;
    float a1 = 0.f, a2 = 0.f, z1 = 0.f, z2 = 0.f;
#pragma unroll
    for (int j = 0; j < 32; j++) {
        float v = __ldg(hp + (size_t)sid[half][j] * 256);
        float w1 = ew1[half][j], w2 = ew2[half][j];
        a1 = fmaf(w1, v, a1);
        a2 = fmaf(w2, v, a2);
        if (d == 0) { z1 += w1; z2 += w2; }
    }
    g_CS1[hb][chunk][d] = a1;
    g_CS2[hb][chunk][d] = a2;
    if (d == 0) { g_ZC1[hb][chunk] = z1; g_ZC2[hb][chunk] = z2; }
}

// ---------------- chunked prefix pass C: write full prefixes, grid 512 -------
__global__ __launch_bounds__(256) void prefixC_kernel()
{
    __shared__ float ew1[2][32], ew2[2][32];
    __shared__ int   sid[2][32];
    int blk = blockIdx.x;
    int hb = blk >> 5, pair = blk & 31;
    int head = hb >> 3, b = hb & 7;
    int base = head * NR + b * 2048;
    int t = threadIdx.x;
    if (t < 64) {
        int ch = t >> 5, jj = t & 31;
        float r = g_rs[base + (2 * pair + ch) * 32 + jj];
        ew1[ch][jj] = expf(r);
        ew2[ch][jj] = expf(LRA * r);
        sid[ch][jj] = g_sidx[base + (2 * pair + ch) * 32 + jj];
    }
    __syncthreads();
    int half = t >> 7, d = t & 127;
    int chunk = 2 * pair + half;
    int j0 = chunk * 32;
    const float* hp = g_h + (size_t)(b * 2048) * 256 + head * 128 + d;
    float a1 = 0.f, a2 = 0.f, z1 = 0.f, z2 = 0.f;
#pragma unroll 8
    for (int c = 0; c < chunk; c++) {
        a1 += g_CS1[hb][c][d];
        a2 += g_CS2[hb][c][d];
        if (d == 0) { z1 += g_ZC1[hb][c]; z2 += g_ZC2[hb][c]; }
    }
    float2* P12 = g_P12 + (size_t)base * 128 + d;
#pragma unroll
    for (int j = 0; j < 32; j++) {
        float v = __ldg(hp + (size_t)sid[half][j] * 256);
        float w1 = ew1[half][j], w2 = ew2[half][j];
        a1 = fmaf(w1, v, a1);
        a2 = fmaf(w2, v, a2);
        float2 pv = {a1, a2};
        P12[(size_t)(j0 + j) * 128] = pv;
        if (d == 0) {
            z1 += w1; z2 += w2;
            float2 zv = {z1, z2};
            g_Z12[base + j0 + j] = zv;
        }
    }
}

// ---------------- per-node O(D) lookup + ELU (hoisted scalars) ---------------
__global__ __launch_bounds__(256) void lookup_kernel(float* xout)
{
    __shared__ float s_ec[2][8], s_eac[2][8], s_wii[2][8], s_idn[2][8];
    __shared__ int   s_m[2][8];
    int b = blockIdx.y;
    int n0 = blockIdx.x * 8;
    int t = threadIdx.x;
    if (t < 16) {
        int hh = t >> 3, nn = t & 7;
        int bb = hh * NR + b * 2048;
        int row = b * 2048 + n0 + nn;
        float c = g_hl[hh * NR + row];
        float ri = g_hr[hh * NR + row];
        float thr = -c;
        const float* rs = &g_rs[bb];
        int lo = 0, hi = 2048;
        while (lo < hi) {
            int mid = (lo + hi) >> 1;
            if (rs[mid] < thr) lo = mid + 1; else hi = mid;
        }
        int m = lo;
        float ec = expf(c), eac = expf(LRA * c);
        float wii = (ri < thr) ? eac * expf(LRA * ri) : ec * expf(ri);
        float2 ztot = g_Z12[bb + 2047];
        float Z1m = 0.f, Z2m = 0.f;
        if (m > 0) {
            float2 zm = g_Z12[bb + m - 1];
            Z1m = zm.x; Z2m = zm.y;
        }
        float denom = ec * (ztot.x - Z1m) + eac * Z2m - wii;
        s_m[hh][nn] = m;
        s_ec[hh][nn] = ec;
        s_eac[hh][nn] = eac;
        s_wii[hh][nn] = wii;
        s_idn[hh][nn] = 1.f / denom;
    }
    __syncthreads();
    int head = t >> 7, d = t & 127;
    int base = head * NR + b * 2048;
    float p1tot = g_P12[((size_t)base + 2047) * 128 + d].x;
#pragma unroll 2
    for (int nn = 0; nn < 8; nn++) {
        int row = b * 2048 + n0 + nn;
        int m = s_m[head][nn];
        float ec = s_ec[head][nn], eac = s_eac[head][nn];
        float wii = s_wii[head][nn], idn = s_idn[head][nn];
        size_t idx = (size_t)row * 256 + head * 128 + d;
        float hid = g_h[idx];
        float P1m = 0.f, P2m = 0.f;
        if (m > 0) {
            float2 pm = g_P12[((size_t)base + m - 1) * 128 + d];
            P1m = pm.x; P2m = pm.y;
        }
        float numer = ec * (p1tot - P1m) + eac * P2m - wii * hid;
        float o = numer * idn + hid;
        float res = (o > 0.f) ? o : expm1f(o);
        if (xout) {
            xout[idx] = res;
        } else {
            __nv_bfloat16 h = __float2bfloat16(res);
            __nv_bfloat16 l = __float2bfloat16(res - __bfloat162float(h));
            g_Xhi[idx] = h;
            g_Xlo[idx] = l;
        }
    }
}

// ---------------- launch ----------------
extern "C" void kernel_launch(void* const* d_in, const int* in_sizes, int n_in,
                              void* d_out, int out_size)
{
    const float* x   = (const float*)d_in[0];
    const float* W00 = (const float*)d_in[2];
    const float* b00 = (const float*)d_in[3];
    const float* a00 = (const float*)d_in[4];
    const float* W01 = (const float*)d_in[5];
    const float* b01 = (const float*)d_in[6];
    const float* a01 = (const float*)d_in[7];
    const float* W10 = (const float*)d_in[8];
    const float* b10 = (const float*)d_in[9];
    const float* a10 = (const float*)d_in[10];
    const float* W11 = (const float*)d_in[11];
    const float* b11 = (const float*)d_in[12];
    const float* a11 = (const float*)d_in[13];
    float* out = (float*)d_out;

    const int GEMM_SMEM = 8 * TILE_B;
    cudaFuncSetAttribute(gemm_mma_kernel,
                         cudaFuncAttributeMaxDynamicSharedMemorySize, GEMM_SMEM);

    pack_kernel<<<512, 256>>>(x, W00, b00, a00, W01, b01, a01,
                              W10, b10, a10, W11, b11, a11);

    // layer 0
    gemm_mma_kernel<<<dim3(2, 128), 256, GEMM_SMEM>>>(0);
    sortA_kernel<<<64, 512>>>();
    sortB_kernel<<<64, 512>>>();
    prefixA_kernel<<<512, 256>>>();
    prefixC_kernel<<<512, 256>>>();
    lookup_kernel<<<dim3(256, 8), 256>>>(nullptr);

    // layer 1
    gemm_mma_kernel<<<dim3(2, 128), 256, GEMM_SMEM>>>(1);
    sortA_kernel<<<64, 512>>>();
    sortB_kernel<<<64, 512>>>();
    prefixA_kernel<<<512, 256>>>();
    prefixC_kernel<<<512, 256>>>();
    lookup_kernel<<<dim3(256, 8), 256>>>(out);
}

// round 14
// speedup vs baseline: 1.9121x; 1.0275x over previous
#include <cuda_runtime.h>
#include <cuda_bf16.h>
#include <cstddef>
#include <cstdint>

#define NB 8
#define NN 2048
#define NR 16384          // NB*NN rows
#define LRA 0.2f

typedef unsigned long long ull;

// ---------------- device scratch ----------------
__device__ float g_h[NR * 256];
__device__ float g_xmid[NR * 256];
__device__ __nv_bfloat16 g_Whi[2][256 * 256];
__device__ __nv_bfloat16 g_Wlo[2][256 * 256];
__device__ float g_bcat[2][256];
__device__ float g_aL[2][2][128];
__device__ float g_aR[2][2][128];
__device__ float g_hl[2 * NR];
__device__ float g_hr[2 * NR];
__device__ float g_rs[2 * NR];
__device__ int   g_sidx[2 * NR];
__device__ ull   g_kv[2 * NR];
__device__ float2 g_P12[2 * NR * 128];  // interleaved {P1,P2}
__device__ float2 g_Z12[2 * NR];        // interleaved {Z1,Z2}
__device__ float g_CS1[16][64][128];
__device__ float g_CS2[16][64][128];
__device__ float g_ZC1[16][64];
__device__ float g_ZC2[16][64];

// ---------------- helpers ----------------
__device__ __forceinline__ uint32_t smem_u32(const void* p) {
    uint32_t a;
    asm("{ .reg .u64 tmp; cvta.to.shared.u64 tmp, %1; cvt.u32.u64 %0, tmp; }"
        : "=r"(a) : "l"(p));
    return a;
}
__device__ __forceinline__ void ldmx4(uint32_t* r, uint32_t addr) {
    asm volatile("ldmatrix.sync.aligned.m8n8.x4.shared.b16 {%0,%1,%2,%3}, [%4];"
        : "=r"(r[0]), "=r"(r[1]), "=r"(r[2]), "=r"(r[3]) : "r"(addr));
}
__device__ __forceinline__ void mma_bf16(float* c, const uint32_t* a, const uint32_t* b) {
    asm volatile("mma.sync.aligned.m16n8k16.row.col.f32.bf16.bf16.f32 "
        "{%0,%1,%2,%3}, {%4,%5,%6,%7}, {%8,%9}, {%0,%1,%2,%3};"
        : "+f"(c[0]), "+f"(c[1]), "+f"(c[2]), "+f"(c[3])
        : "r"(a[0]), "r"(a[1]), "r"(a[2]), "r"(a[3]), "r"(b[0]), "r"(b[1]));
}
__device__ __forceinline__ void cpa16(uint32_t dst, const void* src) {
    asm volatile("cp.async.cg.shared.global [%0], [%1], 16;" :: "r"(dst), "l"(src));
}
#define CP_COMMIT() asm volatile("cp.async.commit_group;" ::: "memory")
#define CP_WAIT1()  asm volatile("cp.async.wait_group 1;" ::: "memory")
#define CP_WAIT0()  asm volatile("cp.async.wait_group 0;" ::: "memory")

__device__ __forceinline__ void cvt_hilo(float4 v, uint2& hi, uint2& lo) {
    __nv_bfloat16 h0 = __float2bfloat16(v.x), h1 = __float2bfloat16(v.y);
    __nv_bfloat16 h2 = __float2bfloat16(v.z), h3 = __float2bfloat16(v.w);
    __nv_bfloat16 l0 = __float2bfloat16(v.x - __bfloat162float(h0));
    __nv_bfloat16 l1 = __float2bfloat16(v.y - __bfloat162float(h1));
    __nv_bfloat16 l2 = __float2bfloat16(v.z - __bfloat162float(h2));
    __nv_bfloat16 l3 = __float2bfloat16(v.w - __bfloat162float(h3));
    hi.x = ((uint32_t)__bfloat16_as_ushort(h1) << 16) | __bfloat16_as_ushort(h0);
    hi.y = ((uint32_t)__bfloat16_as_ushort(h3) << 16) | __bfloat16_as_ushort(h2);
    lo.x = ((uint32_t)__bfloat16_as_ushort(l1) << 16) | __bfloat16_as_ushort(l0);
    lo.y = ((uint32_t)__bfloat16_as_ushort(l3) << 16) | __bfloat16_as_ushort(l2);
}

// ---------------- pack: weights only (bf16 hi/lo, K-major), bias, a ---------
__global__ __launch_bounds__(256) void pack_kernel(
    const float* W00, const float* b00, const float* a00,
    const float* W01, const float* b01, const float* a01,
    const float* W10, const float* b10, const float* a10,
    const float* W11, const float* b11, const float* a11)
{
    const float* Ws[2][2] = {{W00, W01}, {W10, W11}};
    const float* bs[2][2] = {{b00, b01}, {b10, b11}};
    const float* as[2][2] = {{a00, a01}, {a10, a11}};
    int tid = blockIdx.x * blockDim.x + threadIdx.x;
    int nth = gridDim.x * blockDim.x;
    for (int idx = tid; idx < 2 * 256 * 256; idx += nth) {
        int layer = idx >> 16;
        int rem = idx & 0xFFFF;
        int n = rem >> 8, k = rem & 255;
        float w = Ws[layer][n >> 7][k * 128 + (n & 127)];
        __nv_bfloat16 h = __float2bfloat16(w);
        __nv_bfloat16 l = __float2bfloat16(w - __bfloat162float(h));
        g_Whi[layer][rem] = h;
        g_Wlo[layer][rem] = l;
    }
    for (int idx = tid; idx < 2 * 256; idx += nth) {
        int layer = idx >> 8, c = idx & 255;
        g_bcat[layer][c] = bs[layer][c >> 7][c & 127];
    }
    for (int idx = tid; idx < 2 * 2 * 128; idx += nth) {
        int layer = idx >> 8, head = (idx >> 7) & 1, d = idx & 127;
        g_aL[layer][head][d] = as[layer][head][d];
        g_aR[layer][head][d] = as[layer][head][128 + d];
    }
}

// ---------------- HMMA GEMM: A fp32->inline cvt (pipelined), W cp.async -----
#define TILE_B 10240
__device__ __forceinline__ uint32_t tile_off(int b, int w) {
    return (uint32_t)((b * 4 + w) * TILE_B);
}
__device__ __forceinline__ void issue_W(
    uint32_t sb, int bb, int n0, int k0, int t,
    const __nv_bfloat16* Whi, const __nv_bfloat16* Wlo)
{
#pragma unroll
    for (int q = 0; q < 2; q++) {
        int cid = t + q * 256;
        int row = cid >> 2, c8 = cid & 3;
        uint32_t soff = (uint32_t)(row * 80 + c8 * 16);
        size_t gw = (size_t)(n0 + row) * 256 + k0 + c8 * 8;
        cpa16(sb + tile_off(bb, 2) + soff, Whi + gw);
        cpa16(sb + tile_off(bb, 3) + soff, Wlo + gw);
    }
}

__global__ __launch_bounds__(256) void gemm_mma_kernel(const float* __restrict__ Xin, int layer)
{
    extern __shared__ char smem[];
    __shared__ float sHL[128][2], sHR[128][2];
    const float* X = Xin ? Xin : g_xmid;
    uint32_t sb = smem_u32(smem);
    int t = threadIdx.x, lane = t & 31, wid = t >> 5;
    int wm = wid & 3, wn = wid >> 2;
    int m0 = blockIdx.y * 128, n0 = blockIdx.x * 128;
    int head = n0 >> 7;
    const __nv_bfloat16* Whi = g_Whi[layer];
    const __nv_bfloat16* Wlo = g_Wlo[layer];

    float acc[2][8][4];
#pragma unroll
    for (int mi = 0; mi < 2; mi++)
#pragma unroll
        for (int ni = 0; ni < 8; ni++)
#pragma unroll
            for (int q = 0; q < 4; q++) acc[mi][ni][q] = 0.f;

    int arow = wm * 32 + (lane & 7) + (lane & 8);
    int acolx = (lane & 16) >> 1;
    int brow4 = wn * 64 + (lane & 7) + ((lane & 16) >> 1);
    int bcol4 = (lane & 8);

    int lrow = t >> 3, lkq = t & 7;   // A staging: 32-row stride over 4 its

    float4 ra[4];
#pragma unroll
    for (int it = 0; it < 4; it++)
        ra[it] = *(const float4*)(X + (size_t)(m0 + lrow + it * 32) * 256 + lkq * 4);
    issue_W(sb, 0, n0, 0, t, Whi, Wlo);
    CP_COMMIT();

    for (int kt = 0; kt < 8; kt++) {
        int bb = kt & 1;
        // convert + store A tile to smem
#pragma unroll
        for (int it = 0; it < 4; it++) {
            int row = lrow + it * 32;
            uint2 hi, lo;
            cvt_hilo(ra[it], hi, lo);
            uint32_t soff = (uint32_t)(row * 80 + lkq * 8);
            *(uint2*)(smem + tile_off(bb, 0) + soff) = hi;
            *(uint2*)(smem + tile_off(bb, 1) + soff) = lo;
        }
        if (kt < 7) {
            int k0 = (kt + 1) * 32;
#pragma unroll
            for (int it = 0; it < 4; it++)
                ra[it] = *(const float4*)(X + (size_t)(m0 + lrow + it * 32) * 256 + k0 + lkq * 4);
            issue_W(sb, bb ^ 1, n0, k0, t, Whi, Wlo);
            CP_COMMIT();
            CP_WAIT1();
        } else {
            CP_WAIT0();
        }
        __syncthreads();
        uint32_t bA0 = sb + tile_off(bb, 0), bA1 = sb + tile_off(bb, 1);
        uint32_t bB0 = sb + tile_off(bb, 2), bB1 = sb + tile_off(bb, 3);
#pragma unroll
        for (int ks = 0; ks < 32; ks += 16) {
            uint32_t ah[2][4], al[2][4], bh[4][4], bl[4][4];
#pragma unroll
            for (int mi = 0; mi < 2; mi++) {
                uint32_t off = (uint32_t)((arow + mi * 16) * 40 + ks + acolx) * 2;
                ldmx4(ah[mi], bA0 + off);
                ldmx4(al[mi], bA1 + off);
            }
#pragma unroll
            for (int p = 0; p < 4; p++) {
                uint32_t off = (uint32_t)((brow4 + p * 16) * 40 + ks + bcol4) * 2;
                ldmx4(bh[p], bB0 + off);
                ldmx4(bl[p], bB1 + off);
            }
#pragma unroll
            for (int mi = 0; mi < 2; mi++)
#pragma unroll
                for (int ni = 0; ni < 8; ni++) {
                    const uint32_t* bph = &bh[ni >> 1][(ni & 1) * 2];
                    const uint32_t* bpl = &bl[ni >> 1][(ni & 1) * 2];
                    mma_bf16(acc[mi][ni], ah[mi], bph);
                    mma_bf16(acc[mi][ni], ah[mi], bpl);
                    mma_bf16(acc[mi][ni], al[mi], bph);
                }
        }
        __syncthreads();
    }

    int rbase = m0 + wm * 32 + (lane >> 2);
    int cloc = wn * 64 + (lane & 3) * 2;
    float pl[4] = {0.f, 0.f, 0.f, 0.f}, pr[4] = {0.f, 0.f, 0.f, 0.f};
#pragma unroll
    for (int mi = 0; mi < 2; mi++)
#pragma unroll
        for (int ni = 0; ni < 8; ni++) {
            int c0 = cloc + ni * 8;
            int gc = n0 + c0;
            float b0v = g_bcat[layer][gc], b1v = g_bcat[layer][gc + 1];
            float al0 = g_aL[layer][head][c0], al1 = g_aL[layer][head][c0 + 1];
            float ar0 = g_aR[layer][head][c0], ar1 = g_aR[layer][head][c0 + 1];
            int gr = rbase + mi * 16;
            float h00 = acc[mi][ni][0] + b0v, h01 = acc[mi][ni][1] + b1v;
            float h10 = acc[mi][ni][2] + b0v, h11 = acc[mi][ni][3] + b1v;
            float2 p0 = {h00, h01};
            float2 p1 = {h10, h11};
            *(float2*)&g_h[(size_t)gr * 256 + gc] = p0;
            *(float2*)&g_h[(size_t)(gr + 8) * 256 + gc] = p1;
            pl[mi * 2 + 0] += h00 * al0 + h01 * al1;
            pl[mi * 2 + 1] += h10 * al0 + h11 * al1;
            pr[mi * 2 + 0] += h00 * ar0 + h01 * ar1;
            pr[mi * 2 + 1] += h10 * ar0 + h11 * ar1;
        }
#pragma unroll
    for (int off = 1; off < 4; off <<= 1)
#pragma unroll
        for (int r = 0; r < 4; r++) {
            pl[r] += __shfl_xor_sync(0xFFFFFFFFu, pl[r], off);
            pr[r] += __shfl_xor_sync(0xFFFFFFFFu, pr[r], off);
        }
    if ((lane & 3) == 0) {
        int rloc = wm * 32 + (lane >> 2);
#pragma unroll
        for (int r = 0; r < 4; r++) {
            sHL[rloc + r * 8][wn] = pl[r];
            sHR[rloc + r * 8][wn] = pr[r];
        }
    }
    __syncthreads();
    if (t < 128) {
        g_hl[head * NR + m0 + t] = sHL[t][0] + sHL[t][1];
        g_hr[head * NR + m0 + t] = sHR[t][0] + sHR[t][1];
    }
}

// ---------------- sort stage 1 ----------------
__device__ __forceinline__ ull bswap_reg(ull v, int j, bool up, int i) {
    ull pv = __shfl_xor_sync(0xFFFFFFFFu, v, j);
    bool lower = ((i & j) == 0);
    return (lower == up) ? (v < pv ? v : pv) : (v > pv ? v : pv);
}

__global__ __launch_bounds__(512) void sortA_kernel()
{
    __shared__ ull kv[512];
    int bid = blockIdx.x;
    int sg = bid >> 2, r = bid & 3;
    int base = (sg >> 3) * NR + (sg & 7) * 2048;
    int i = threadIdx.x;
    int gi = r * 512 + i;

    unsigned u = __float_as_uint(g_hr[base + gi]);
    u ^= (u >> 31) ? 0xFFFFFFFFu : 0x80000000u;
    ull v = ((ull)u << 32) | (unsigned)gi;

#pragma unroll
    for (int k = 2; k <= 32; k <<= 1) {
        bool up = ((i & k) == 0);
        for (int j = k >> 1; j >= 1; j >>= 1)
            v = bswap_reg(v, j, up, i);
    }
    kv[i] = v;
    __syncthreads();

    for (int k = 64; k <= 512; k <<= 1) {
        for (int j = k >> 1; j >= 32; j >>= 1) {
            int ixj = i ^ j;
            if (ixj > i) {
                bool up = ((i & k) == 0);
                ull a = kv[i], b = kv[ixj];
                if ((a > b) == up) { kv[i] = b; kv[ixj] = a; }
            }
            __syncthreads();
        }
        v = kv[i];
        bool up = ((i & k) == 0);
        for (int j = 16; j >= 1; j >>= 1)
            v = bswap_reg(v, j, up, i);
        if (k < 512) { kv[i] = v; __syncthreads(); }
    }
    g_kv[base + gi] = v;
}

// ---------------- sort stage 2: rank merge (smem-staged) ----------------
__global__ __launch_bounds__(512) void sortB_kernel()
{
    __shared__ ull runs[2048];
    int bid = blockIdx.x;
    int sg = bid >> 2, r = bid & 3;
    int base = (sg >> 3) * NR + (sg & 7) * 2048;
    int i = threadIdx.x;
#pragma unroll
    for (int q = 0; q < 4; q++)
        runs[i + q * 512] = g_kv[base + i + q * 512];
    __syncthreads();

    ull v = runs[r * 512 + i];
    int rank = i;
#pragma unroll
    for (int rr = 0; rr < 4; rr++) {
        if (rr == r) continue;
        const ull* run = &runs[rr * 512];
        int lo = 0, hi = 512;
#pragma unroll
        for (int s = 0; s < 10; s++) {
            if (lo < hi) {
                int mid = (lo + hi) >> 1;
                if (run[mid] < v) lo = mid + 1; else hi = mid;
            }
        }
        rank += lo;
    }
    unsigned u = (unsigned)(v >> 32);
    u ^= (u >> 31) ? 0x80000000u : 0xFFFFFFFFu;
    g_rs[base + rank] = __uint_as_float(u);
    g_sidx[base + rank] = (int)(v & 0xFFFFFFFFu);
}

// ---------------- chunked prefix pass A: per-chunk (32) sums, grid 512 -------
__global__ __launch_bounds__(256) void prefixA_kernel()
{
    __shared__ float ew1[2][32], ew2[2][32];
    __shared__ int   sid[2][32];
    int blk = blockIdx.x;
    int hb = blk >> 5, pair = blk & 31;
    int head = hb >> 3, b = hb & 7;
    int base = head * NR + b * 2048;
    int t = threadIdx.x;
    if (t < 64) {
        int ch = t >> 5, jj = t & 31;
        float r = g_rs[base + (2 * pair + ch) * 32 + jj];
        ew1[ch][jj] = expf(r);
        ew2[ch][jj] = expf(LRA * r);
        sid[ch][jj] = g_sidx[base + (2 * pair + ch) * 32 + jj];
    }
    __syncthreads();
    int half = t >> 7, d = t & 127;
    int chunk = 2 * pair + half;
    const float* hp = g_h + (size_t)(b * 2048) * 256 + head * 128 + d;
    float a1 = 0.f, a2 = 0.f, z1 = 0.f, z2 = 0.f;
#pragma unroll
    for (int j = 0; j < 32; j++) {
        float v = __ldg(hp + (size_t)sid[half][j] * 256);
        float w1 = ew1[half][j], w2 = ew2[half][j];
        a1 = fmaf(w1, v, a1);
        a2 = fmaf(w2, v, a2);
        if (d == 0) { z1 += w1; z2 += w2; }
    }
    g_CS1[hb][chunk][d] = a1;
    g_CS2[hb][chunk][d] = a2;
    if (d == 0) { g_ZC1[hb][chunk] = z1; g_ZC2[hb][chunk] = z2; }
}

// ---------------- chunked prefix pass C: write full prefixes, grid 512 -------
__global__ __launch_bounds__(256) void prefixC_kernel()
{
    __shared__ float ew1[2][32], ew2[2][32];
    __shared__ int   sid[2][32];
    int blk = blockIdx.x;
    int hb = blk >> 5, pair = blk & 31;
    int head = hb >> 3, b = hb & 7;
    int base = head * NR + b * 2048;
    int t = threadIdx.x;
    if (t < 64) {
        int ch = t >> 5, jj = t & 31;
        float r = g_rs[base + (2 * pair + ch) * 32 + jj];
        ew1[ch][jj] = expf(r);
        ew2[ch][jj] = expf(LRA * r);
        sid[ch][jj] = g_sidx[base + (2 * pair + ch) * 32 + jj];
    }
    __syncthreads();
    int half = t >> 7, d = t & 127;
    int chunk = 2 * pair + half;
    int j0 = chunk * 32;
    const float* hp = g_h + (size_t)(b * 2048) * 256 + head * 128 + d;
    float a1 = 0.f, a2 = 0.f, z1 = 0.f, z2 = 0.f;
#pragma unroll 8
    for (int c = 0; c < chunk; c++) {
        a1 += g_CS1[hb][c][d];
        a2 += g_CS2[hb][c][d];
        if (d == 0) { z1 += g_ZC1[hb][c]; z2 += g_ZC2[hb][c]; }
    }
    float2* P12 = g_P12 + (size_t)base * 128 + d;
#pragma unroll
    for (int j = 0; j < 32; j++) {
        float v = __ldg(hp + (size_t)sid[half][j] * 256);
        float w1 = ew1[half][j], w2 = ew2[half][j];
        a1 = fmaf(w1, v, a1);
        a2 = fmaf(w2, v, a2);
        float2 pv = {a1, a2};
        P12[(size_t)(j0 + j) * 128] = pv;
        if (d == 0) {
            z1 += w1; z2 += w2;
            float2 zv = {z1, z2};
            g_Z12[base + j0 + j] = zv;
        }
    }
}

// ---------------- per-node O(D) lookup + ELU (hoisted scalars) ---------------
__global__ __launch_bounds__(256) void lookup_kernel(float* xout)
{
    __shared__ float s_ec[2][8], s_eac[2][8], s_wii[2][8], s_idn[2][8];
    __shared__ int   s_m[2][8];
    float* xo = xout ? xout : g_xmid;
    int b = blockIdx.y;
    int n0 = blockIdx.x * 8;
    int t = threadIdx.x;
    if (t < 16) {
        int hh = t >> 3, nn = t & 7;
        int bb = hh * NR + b * 2048;
        int row = b * 2048 + n0 + nn;
        float c = g_hl[hh * NR + row];
        float ri = g_hr[hh * NR + row];
        float thr = -c;
        const float* rs = &g_rs[bb];
        int lo = 0, hi = 2048;
        while (lo < hi) {
            int mid = (lo + hi) >> 1;
            if (rs[mid] < thr) lo = mid + 1; else hi = mid;
        }
        int m = lo;
        float ec = expf(c), eac = expf(LRA * c);
        float wii = (ri < thr) ? eac * expf(LRA * ri) : ec * expf(ri);
        float2 ztot = g_Z12[bb + 2047];
        float Z1m = 0.f, Z2m = 0.f;
        if (m > 0) {
            float2 zm = g_Z12[bb + m - 1];
            Z1m = zm.x; Z2m = zm.y;
        }
        float denom = ec * (ztot.x - Z1m) + eac * Z2m - wii;
        s_m[hh][nn] = m;
        s_ec[hh][nn] = ec;
        s_eac[hh][nn] = eac;
        s_wii[hh][nn] = wii;
        s_idn[hh][nn] = 1.f / denom;
    }
    __syncthreads();
    int head = t >> 7, d = t & 127;
    int base = head * NR + b * 2048;
    float p1tot = g_P12[((size_t)base + 2047) * 128 + d].x;
#pragma unroll 2
    for (int nn = 0; nn < 8; nn++) {
        int row = b * 2048 + n0 + nn;
        int m = s_m[head][nn];
        float ec = s_ec[head][nn], eac = s_eac[head][nn];
        float wii = s_wii[head][nn], idn = s_idn[head][nn];
        size_t idx = (size_t)row * 256 + head * 128 + d;
        float hid = g_h[idx];
        float P1m = 0.f, P2m = 0.f;
        if (m > 0) {
            float2 pm = g_P12[((size_t)base + m - 1) * 128 + d];
            P1m = pm.x; P2m = pm.y;
        }
        float numer = ec * (p1tot - P1m) + eac * P2m - wii * hid;
        float o = numer * idn + hid;
        xo[idx] = (o > 0.f) ? o : expm1f(o);
    }
}

// ---------------- launch ----------------
extern "C" void kernel_launch(void* const* d_in, const int* in_sizes, int n_in,
                              void* d_out, int out_size)
{
    const float* x   = (const float*)d_in[0];
    const float* W00 = (const float*)d_in[2];
    const float* b00 = (const float*)d_in[3];
    const float* a00 = (const float*)d_in[4];
    const float* W01 = (const float*)d_in[5];
    const float* b01 = (const float*)d_in[6];
    const float* a01 = (const float*)d_in[7];
    const float* W10 = (const float*)d_in[8];
    const float* b10 = (const float*)d_in[9];
    const float* a10 = (const float*)d_in[10];
    const float* W11 = (const float*)d_in[11];
    const float* b11 = (const float*)d_in[12];
    const float* a11 = (const float*)d_in[13];
    float* out = (float*)d_out;

    const int GEMM_SMEM = 8 * TILE_B;
    cudaFuncSetAttribute(gemm_mma_kernel,
                         cudaFuncAttributeMaxDynamicSharedMemorySize, GEMM_SMEM);

    pack_kernel<<<128, 256>>>(W00, b00, a00, W01, b01, a01,
                              W10, b10, a10, W11, b11, a11);

    // layer 0
    gemm_mma_kernel<<<dim3(2, 128), 256, GEMM_SMEM>>>(x, 0);
    sortA_kernel<<<64, 512>>>();
    sortB_kernel<<<64, 512>>>();
    prefixA_kernel<<<512, 256>>>();
    prefixC_kernel<<<512, 256>>>();
    lookup_kernel<<<dim3(256, 8), 256>>>(nullptr);

    // layer 1
    gemm_mma_kernel<<<dim3(2, 128), 256, GEMM_SMEM>>>(nullptr, 1);
    sortA_kernel<<<64, 512>>>();
    sortB_kernel<<<64, 512>>>();
    prefixA_kernel<<<512, 256>>>();
    prefixC_kernel<<<512, 256>>>();
    lookup_kernel<<<dim3(256, 8), 256>>>(out);
}